// round 6
// baseline (speedup 1.0000x reference)
#include <cuda_runtime.h>

// x: (32,3,16,32,32) fp32; weight: (3,16,3,3,3); bias scalar; out: (32,1,31,63,63)
// ConvTranspose3d s=2 p=1 k=3: per dim even o -> tap k=1 (i=o/2);
// odd o -> k=0 (i=(o+1)/2), k=2 (i=(o-1)/2). All in-range for these shapes.

#define DIN 16
#define HIN 32
#define WIN 32
#define XCH (DIN*HIN*WIN)   // 16384
#define XB  (3*XCH)         // 49152
#define GSTR 20             // floats per (oc,kd,kh) group: 9 dup'd pairs (18) + 2 pad
#define WSH (16*9*GSTR)     // 2880 floats = 11.5 KB

typedef unsigned long long ull;

__device__ __forceinline__ ull pk(float lo, float hi) {
    ull r; asm("mov.b64 %0, {%1, %2};" : "=l"(r) : "f"(lo), "f"(hi)); return r;
}
__device__ __forceinline__ float2 unpk(ull v) {
    float lo, hi; asm("mov.b64 {%0, %1}, %2;" : "=f"(lo), "=f"(hi) : "l"(v));
    return make_float2(lo, hi);
}
// d.lo += w.lo*x.lo; d.hi += w.hi*x.hi  (two independent rn-FMAs: bit-exact vs scalar)
__device__ __forceinline__ void ffma2(ull &d, ull w, ull x) {
    asm("fma.rn.f32x2 %0, %1, %2, %0;" : "+l"(d) : "l"(w), "l"(x));
}

// Each thread: 4 consecutive outputs ow = 4c..4c+3 (c = lane&15; c==15's ow=63 masked).
//   even pair (ow=4c, 4c+2):  kw=1 @ (j0, j1)          -> x-pair E = (x[j0], x[j1])
//   odd  pair (ow=4c+1,4c+3): kw=0 @ (j1, j2) -> O pair; kw=2 @ (j0, j1) -> reuse E
// Weights in shared as duplicated pairs (w,w): one dup'd group feeds both halves.
template<int ND, int NH>
__device__ __forceinline__ void run_quad(
    const float* __restrict__ xb, const float* __restrict__ sw,
    float* __restrict__ op, int id0, int id1, int ih0, int ih1, int c, float bv)
{
    ull E[ND][NH][3], O[ND][NH][3];
    int iw0 = 2 * c;
    int iw2 = (c < 15) ? iw0 + 2 : 31;   // clamp; only feeds masked ow=63
    #pragma unroll
    for (int a = 0; a < ND; a++) {
        int idv = (a == 0) ? id0 : id1;
        #pragma unroll
        for (int h = 0; h < NH; h++) {
            int ihv = (h == 0) ? ih0 : ih1;
            const float* p = xb + idv * (HIN * WIN) + ihv * WIN;
            #pragma unroll
            for (int ic = 0; ic < 3; ic++) {
                const float* q = p + ic * XCH;
                float2 t = __ldg((const float2*)(q + iw0));   // 8B aligned (iw0 even)
                float x2 = __ldg(q + iw2);
                E[a][h][ic] = pk(t.x, t.y);
                O[a][h][ic] = pk(t.y, x2);
            }
        }
    }

    // Streaming logsumexp (conv values bounded ~|5| for this data; fp32 exp safe @1e-3)
    float s0 = 0.f, s1 = 0.f, s2 = 0.f, s3 = 0.f;
    #pragma unroll
    for (int oc = 0; oc < 16; oc++) {
        ull Ve = 0ull, Vo = 0ull;   // packed (v0,v2) and (v1,v3); 0 bits == (0.f,0.f)
        #pragma unroll
        for (int a = 0; a < ND; a++) {
            const int KD = (ND == 1) ? 1 : a * 2;
            #pragma unroll
            for (int h = 0; h < NH; h++) {
                const int KH = (NH == 1) ? 1 : h * 2;
                const float* gf = sw + ((oc * 3 + KD) * 3 + KH) * GSTR;
                const ulonglong2* g = (const ulonglong2*)gf;     // 16B aligned
                ulonglong2 W01 = g[0];   // dup'd pairs s0,s1
                ulonglong2 W23 = g[1];   // s2,s3
                ulonglong2 W45 = g[2];   // s4,s5
                ulonglong2 W67 = g[3];   // s6,s7
                ull        W8  = ((const ull*)gf)[8];  // s8
                // even: kw=1 slots (1,4,7)
                ffma2(Ve, W01.y, E[a][h][0]);
                ffma2(Ve, W45.x, E[a][h][1]);
                ffma2(Ve, W67.y, E[a][h][2]);
                // odd: kw=0 slots (0,3,6) with O; kw=2 slots (2,5,8) with E
                ffma2(Vo, W01.x, O[a][h][0]);
                ffma2(Vo, W23.y, O[a][h][1]);
                ffma2(Vo, W67.x, O[a][h][2]);
                ffma2(Vo, W23.x, E[a][h][0]);
                ffma2(Vo, W45.y, E[a][h][1]);
                ffma2(Vo, W8,    E[a][h][2]);
            }
        }
        float2 e = unpk(Ve), o = unpk(Vo);
        s0 += __expf(e.x); s2 += __expf(e.y);
        s1 += __expf(o.x); s3 += __expf(o.y);
    }

    float l0 = __logf(s0), l1 = __logf(s1), l2 = __logf(s2), l3 = __logf(s3);
    float h0 = __fdividef(l0, 6.f * (1.f + __expf(-(l0 + 3.f))));
    float h1 = __fdividef(l1, 6.f * (1.f + __expf(-(l1 + 3.f))));
    float h2 = __fdividef(l2, 6.f * (1.f + __expf(-(l2 + 3.f))));
    float h3 = __fdividef(l3, 6.f * (1.f + __expf(-(l3 + 3.f))));
    int wb = 4 * c;
    op[wb]     = fminf(fmaxf(h0 - bv, -1.f), 1.f);
    op[wb + 1] = fminf(fmaxf(h1 - bv, -1.f), 1.f);
    op[wb + 2] = fminf(fmaxf(h2 - bv, -1.f), 1.f);
    if (wb + 3 < 63) op[wb + 3] = fminf(fmaxf(h3 - bv, -1.f), 1.f);
}

__global__ __launch_bounds__(256)
void fused_convT_lse_hs_v6(
    const float* __restrict__ x,
    const float* __restrict__ w,
    const float* __restrict__ bias,
    float* __restrict__ out)
{
    __shared__ __align__(16) float sw[WSH];
    // src w[ic*432 + oc*27 + kd*9 + kh*3 + kw] -> dup'd pair pack
    for (int i = threadIdx.x; i < 1296; i += 256) {
        int ic = i / 432;  int r = i - ic * 432;
        int oc = r / 27;   int tap = r - oc * 27;
        int kd = tap / 9;  int t2 = tap - kd * 9;
        int kh = t2 / 3;   int kw = t2 - kh * 3;
        int s  = ic * 3 + kw;
        float v = w[i];
        float* dst = sw + ((oc * 3 + kd) * 3 + kh) * GSTR + 2 * s;
        dst[0] = v;
        dst[1] = v;
    }
    __syncthreads();

    int warp = threadIdx.x >> 5;
    int lane = threadIdx.x & 31;
    int half = lane >> 4;          // 2 rows per warp (same parity class)
    int c    = lane & 15;

    int gw = blockIdx.x * 8 + warp;   // class-concatenated warp id
    // Class warp counts: 8192 / 7936 / 7680 / 7440 (all %8==0), total 31248.
    int cls, r;
    if (gw < 8192)       { cls = 0; r = 2 * gw + half; }
    else if (gw < 16128) { cls = 1; r = 2 * (gw - 8192) + half; }
    else if (gw < 23808) { cls = 2; r = 2 * (gw - 16128) + half; }
    else                 { cls = 3; r = 2 * (gw - 23808) + half; }

    int pd = cls >> 1, ph = cls & 1;
    int nhc = ph ? 31 : 32;
    int per_b = (pd ? 15 : 16) * nhc;
    int b = r / per_b; int rem = r - b * per_b;
    int idd = rem / nhc; int ihh = rem - idd * nhc;
    int od = 2 * idd + pd, oh = 2 * ihh + ph;

    const float* xb = x + (size_t)b * XB;
    float* op = out + ((size_t)(b * 31 + od) * 63 + oh) * 63;
    float bv = __ldg(bias);

    int id0, id1 = 0, ih0, ih1 = 0;
    if (pd) { id0 = (od + 1) >> 1; id1 = (od - 1) >> 1; } else id0 = od >> 1;
    if (ph) { ih0 = (oh + 1) >> 1; ih1 = (oh - 1) >> 1; } else ih0 = oh >> 1;

    if (cls == 0)      run_quad<1, 1>(xb, sw, op, id0, id1, ih0, ih1, c, bv);
    else if (cls == 1) run_quad<1, 2>(xb, sw, op, id0, id1, ih0, ih1, c, bv);
    else if (cls == 2) run_quad<2, 1>(xb, sw, op, id0, id1, ih0, ih1, c, bv);
    else               run_quad<2, 2>(xb, sw, op, id0, id1, ih0, ih1, c, bv);
}

extern "C" void kernel_launch(void* const* d_in, const int* in_sizes, int n_in,
                              void* d_out, int out_size)
{
    const float* x    = (const float*)d_in[0];
    const float* w    = (const float*)d_in[1];
    const float* bias = (const float*)d_in[2];
    float* out        = (float*)d_out;
    // 31248 warps, 8 per block -> 3906 blocks
    fused_convT_lse_hs_v6<<<3906, 256>>>(x, w, bias, out);
}

// round 7
// speedup vs baseline: 1.1501x; 1.1501x over previous
#include <cuda_runtime.h>

// x: (32,3,16,32,32) fp32; weight: (3,16,3,3,3); bias scalar; out: (32,1,31,63,63)
// ConvTranspose3d s=2 p=1 k=3: per dim even o -> tap k=1 (i=o/2);
// odd o -> k=0 (i=(o+1)/2), k=2 (i=(o-1)/2). All in-range (od<=30, oh/ow<=62).

#define DIN 16
#define HIN 32
#define WIN 32
#define XCH (DIN*HIN*WIN)   // 16384
#define XB  (3*XCH)         // 49152
#define WSH (16*3*3*12)     // sw[oc][kd][kh][slot], slot=ic*3+kw (9 used, pad 12)

__device__ __forceinline__ void load_weights(const float* __restrict__ w, float* sw) {
    // src w[ic*432 + oc*27 + kd*9 + kh*3 + kw]
    for (int i = threadIdx.x; i < 1296; i += 256) {
        int ic = i / 432;  int r = i - ic * 432;
        int oc = r / 27;   int tap = r - oc * 27;
        int kd = tap / 9;  int t2 = tap - kd * 9;
        int kh = t2 / 3;   int kw = t2 - kh * 3;
        sw[((oc * 3 + kd) * 3 + kh) * 12 + ic * 3 + kw] = w[i];
    }
}

__device__ __forceinline__ float finish(float s, float bv) {
    float l = __logf(s);
    float h = __fdividef(l, 6.f * (1.f + __expf(-(l + 3.f))));
    return fminf(fmaxf(h - bv, -1.f), 1.f);
}

// ---------------- width-8 path (classes with ND*NH <= 2) ----------------
// Lane c = lane&7 handles ow = 8c..8c+7 (c==7: ow 63 masked). 4 rows per warp.
// Even ow=8c+2t: kw1 @ iw=4c+t. Odd ow=8c+2t+1: kw0 @ iw=4c+t+1, kw2 @ iw=4c+t.
template<int ND, int NH>
__device__ __forceinline__ void run_oct(
    const float* __restrict__ xb, const float* __restrict__ sw,
    float* __restrict__ op, int id0, int id1, int ih0, int ih1, int c, float bv)
{
    float xv[ND][NH][3][5];
    int iw0 = 4 * c;
    int iw4 = (c < 7) ? iw0 + 4 : 31;   // clamp; only feeds masked ow=63
    #pragma unroll
    for (int a = 0; a < ND; a++) {
        int idv = (a == 0) ? id0 : id1;
        #pragma unroll
        for (int h = 0; h < NH; h++) {
            int ihv = (h == 0) ? ih0 : ih1;
            const float* p = xb + idv * (HIN * WIN) + ihv * WIN;
            #pragma unroll
            for (int ic = 0; ic < 3; ic++) {
                const float* q = p + ic * XCH;
                float4 t = __ldg((const float4*)(q + iw0));  // 16B aligned (iw0%4==0)
                xv[a][h][ic][0] = t.x; xv[a][h][ic][1] = t.y;
                xv[a][h][ic][2] = t.z; xv[a][h][ic][3] = t.w;
                xv[a][h][ic][4] = __ldg(q + iw4);
            }
        }
    }

    // Streaming logsumexp (conv values bounded ~|5| for this data; fp32 exp safe @1e-3)
    float s[8];
    #pragma unroll
    for (int k = 0; k < 8; k++) s[k] = 0.f;

    #pragma unroll
    for (int oc = 0; oc < 16; oc++) {
        float v[8];
        #pragma unroll
        for (int k = 0; k < 8; k++) v[k] = 0.f;
        #pragma unroll
        for (int a = 0; a < ND; a++) {
            const int KD = (ND == 1) ? 1 : a * 2;
            #pragma unroll
            for (int h = 0; h < NH; h++) {
                const int KH = (NH == 1) ? 1 : h * 2;
                const float* g = sw + ((oc * 3 + KD) * 3 + KH) * 12;
                float4 A = *(const float4*)g;        // slots 0..3
                float4 B = *(const float4*)(g + 4);  // slots 4..7
                float  C = g[8];                     // slot 8
                #pragma unroll
                for (int t = 0; t < 4; t++) {
                    float x0t = xv[a][h][0][t], x1t = xv[a][h][1][t], x2t = xv[a][h][2][t];
                    float x0n = xv[a][h][0][t+1], x1n = xv[a][h][1][t+1], x2n = xv[a][h][2][t+1];
                    // even: kw1 slots 1,4,7
                    v[2*t]   = fmaf(A.y, x0t, v[2*t]);
                    v[2*t]   = fmaf(B.x, x1t, v[2*t]);
                    v[2*t]   = fmaf(B.w, x2t, v[2*t]);
                    // odd: kw0 slots 0,3,6 @ t+1; kw2 slots 2,5,8 @ t
                    v[2*t+1] = fmaf(A.x, x0n, v[2*t+1]);
                    v[2*t+1] = fmaf(A.w, x1n, v[2*t+1]);
                    v[2*t+1] = fmaf(B.z, x2n, v[2*t+1]);
                    v[2*t+1] = fmaf(A.z, x0t, v[2*t+1]);
                    v[2*t+1] = fmaf(B.y, x1t, v[2*t+1]);
                    v[2*t+1] = fmaf(C,   x2t, v[2*t+1]);
                }
            }
        }
        #pragma unroll
        for (int k = 0; k < 8; k++) s[k] += __expf(v[k]);
    }

    int wb = 8 * c;
    #pragma unroll
    for (int k = 0; k < 7; k++) op[wb + k] = finish(s[k], bv);
    if (c < 7) op[wb + 7] = finish(s[7], bv);
}

// Kernel A: classes 0 (ee), 1 (eo), 2 (oe); width 8, 32 rows per block.
// Blocks: cls0 512 | cls1 496 | cls2 480  (rows 16384 / 15872 / 15360)
__global__ __launch_bounds__(256)
void convT_lse_A(const float* __restrict__ x, const float* __restrict__ w,
                 const float* __restrict__ bias, float* __restrict__ out)
{
    __shared__ __align__(16) float sw[WSH];
    load_weights(w, sw);
    __syncthreads();

    int warp = threadIdx.x >> 5, lane = threadIdx.x & 31;
    int rloc = lane >> 3, c = lane & 7;

    int blk = blockIdx.x, cls, rb;
    if (blk < 512)       { cls = 0; rb = blk * 32; }
    else if (blk < 1008) { cls = 1; rb = (blk - 512) * 32; }
    else                 { cls = 2; rb = (blk - 1008) * 32; }
    int r = rb + warp * 4 + rloc;

    int pd = (cls == 2), ph = (cls == 1);
    int nhc = ph ? 31 : 32;
    int per_b = (pd ? 15 : 16) * nhc;
    int b = r / per_b; int rem = r - b * per_b;
    int idd = rem / nhc; int ihh = rem - idd * nhc;
    int od = 2 * idd + pd, oh = 2 * ihh + ph;

    const float* xb = x + (size_t)b * XB;
    float* op = out + ((size_t)(b * 31 + od) * 63 + oh) * 63;
    float bv = __ldg(bias);

    int id0, id1 = 0, ih0, ih1 = 0;
    if (pd) { id0 = (od + 1) >> 1; id1 = (od - 1) >> 1; } else id0 = od >> 1;
    if (ph) { ih0 = (oh + 1) >> 1; ih1 = (oh - 1) >> 1; } else ih0 = oh >> 1;

    if (cls == 0)      run_oct<1, 1>(xb, sw, op, id0, id1, ih0, ih1, c, bv);
    else if (cls == 1) run_oct<1, 2>(xb, sw, op, id0, id1, ih0, ih1, c, bv);
    else               run_oct<2, 1>(xb, sw, op, id0, id1, ih0, ih1, c, bv);
}

// ---------------- width-4 path (class 3: odd od, odd oh) — v5's proven quad ----------
__global__ __launch_bounds__(256)
void convT_lse_B(const float* __restrict__ x, const float* __restrict__ w,
                 const float* __restrict__ bias, float* __restrict__ out)
{
    __shared__ __align__(16) float sw[WSH];
    load_weights(w, sw);
    __syncthreads();

    int warp = threadIdx.x >> 5, lane = threadIdx.x & 31;
    int half = lane >> 4, c = lane & 15;
    int gw = blockIdx.x * 8 + warp;
    int r = 2 * gw + half;              // 14880 rows

    const int per_b = 15 * 31;          // 465
    int b = r / per_b; int rem = r - b * per_b;
    int idd = rem / 31; int ihh = rem - idd * 31;
    int od = 2 * idd + 1, oh = 2 * ihh + 1;

    const float* xb = x + (size_t)b * XB;
    float* op = out + ((size_t)(b * 31 + od) * 63 + oh) * 63;
    float bv = __ldg(bias);

    int id0 = (od + 1) >> 1, id1 = (od - 1) >> 1;
    int ih0 = (oh + 1) >> 1, ih1 = (oh - 1) >> 1;

    // inline quad (ND=NH=2)
    float xv[2][2][3][3];
    int iw0 = 2 * c;
    int iw2 = (c < 15) ? iw0 + 2 : 31;
    #pragma unroll
    for (int a = 0; a < 2; a++) {
        int idv = (a == 0) ? id0 : id1;
        #pragma unroll
        for (int h = 0; h < 2; h++) {
            int ihv = (h == 0) ? ih0 : ih1;
            const float* p = xb + idv * (HIN * WIN) + ihv * WIN;
            #pragma unroll
            for (int ic = 0; ic < 3; ic++) {
                const float* q = p + ic * XCH;
                float2 t = __ldg((const float2*)(q + iw0));
                xv[a][h][ic][0] = t.x;
                xv[a][h][ic][1] = t.y;
                xv[a][h][ic][2] = __ldg(q + iw2);
            }
        }
    }

    float s0 = 0.f, s1 = 0.f, s2 = 0.f, s3 = 0.f;
    #pragma unroll
    for (int oc = 0; oc < 16; oc++) {
        float v0 = 0.f, v1 = 0.f, v2 = 0.f, v3 = 0.f;
        #pragma unroll
        for (int a = 0; a < 2; a++) {
            const int KD = a * 2;
            #pragma unroll
            for (int h = 0; h < 2; h++) {
                const int KH = h * 2;
                const float* g = sw + ((oc * 3 + KD) * 3 + KH) * 12;
                float4 A = *(const float4*)g;
                float4 B = *(const float4*)(g + 4);
                float  C = g[8];
                float x00 = xv[a][h][0][0], x01 = xv[a][h][0][1], x02 = xv[a][h][0][2];
                float x10 = xv[a][h][1][0], x11 = xv[a][h][1][1], x12 = xv[a][h][1][2];
                float x20 = xv[a][h][2][0], x21 = xv[a][h][2][1], x22 = xv[a][h][2][2];
                v0 = fmaf(A.y, x00, v0); v0 = fmaf(B.x, x10, v0); v0 = fmaf(B.w, x20, v0);
                v2 = fmaf(A.y, x01, v2); v2 = fmaf(B.x, x11, v2); v2 = fmaf(B.w, x21, v2);
                v1 = fmaf(A.x, x01, v1); v1 = fmaf(A.w, x11, v1); v1 = fmaf(B.z, x21, v1);
                v1 = fmaf(A.z, x00, v1); v1 = fmaf(B.y, x10, v1); v1 = fmaf(C,   x20, v1);
                v3 = fmaf(A.x, x02, v3); v3 = fmaf(A.w, x12, v3); v3 = fmaf(B.z, x22, v3);
                v3 = fmaf(A.z, x01, v3); v3 = fmaf(B.y, x11, v3); v3 = fmaf(C,   x21, v3);
            }
        }
        s0 += __expf(v0); s1 += __expf(v1); s2 += __expf(v2); s3 += __expf(v3);
    }

    int wb = 4 * c;
    op[wb]     = finish(s0, bv);
    op[wb + 1] = finish(s1, bv);
    op[wb + 2] = finish(s2, bv);
    if (wb + 3 < 63) op[wb + 3] = finish(s3, bv);
}

extern "C" void kernel_launch(void* const* d_in, const int* in_sizes, int n_in,
                              void* d_out, int out_size)
{
    const float* x    = (const float*)d_in[0];
    const float* w    = (const float*)d_in[1];
    const float* bias = (const float*)d_in[2];
    float* out        = (float*)d_out;

    convT_lse_A<<<1488, 256>>>(x, w, bias, out);   // cls0/1/2, width 8
    convT_lse_B<<<930, 256>>>(x, w, bias, out);    // cls3, width 4
}

// round 8
// speedup vs baseline: 1.2054x; 1.0480x over previous
#include <cuda_runtime.h>

// x: (32,3,16,32,32) fp32; weight: (3,16,3,3,3); bias scalar; out: (32,1,31,63,63)
// ConvTranspose3d s=2 p=1 k=3: per dim even o -> tap k=1 (i=o/2);
// odd o -> k=0 (i=(o+1)/2), k=2 (i=(o-1)/2). All in-range (od<=30, oh/ow<=62).

#define DIN 16
#define HIN 32
#define WIN 32
#define XCH (DIN*HIN*WIN)   // 16384
#define XB  (3*XCH)         // 49152
#define WSH (16*3*3*12)     // sw[oc][kd][kh][slot], slot=ic*3+kw (9 used, pad 12)

__device__ __forceinline__ void load_weights(const float* __restrict__ w, float* sw) {
    // src w[ic*432 + oc*27 + kd*9 + kh*3 + kw]
    for (int i = threadIdx.x; i < 1296; i += 256) {
        int ic = i / 432;  int r = i - ic * 432;
        int oc = r / 27;   int tap = r - oc * 27;
        int kd = tap / 9;  int t2 = tap - kd * 9;
        int kh = t2 / 3;   int kw = t2 - kh * 3;
        sw[((oc * 3 + kd) * 3 + kh) * 12 + ic * 3 + kw] = w[i];
    }
}

__device__ __forceinline__ float finish(float s, float bv) {
    float l = __logf(s);
    float h = __fdividef(l, 6.f * (1.f + __expf(-(l + 3.f))));
    return fminf(fmaxf(h - bv, -1.f), 1.f);
}

// ---------------- width-8 path (classes with ND*NH <= 2) ----------------
// Lane c = lane&7 handles ow = 8c..8c+7 (c==7: ow 63 masked). 4 rows per warp.
template<int ND, int NH>
__device__ __forceinline__ void run_oct(
    const float* __restrict__ xb, const float* __restrict__ sw,
    float* __restrict__ op, int id0, int id1, int ih0, int ih1, int c, float bv)
{
    float xv[ND][NH][3][5];
    int iw0 = 4 * c;
    int iw4 = (c < 7) ? iw0 + 4 : 31;   // clamp; only feeds masked ow=63
    #pragma unroll
    for (int a = 0; a < ND; a++) {
        int idv = (a == 0) ? id0 : id1;
        #pragma unroll
        for (int h = 0; h < NH; h++) {
            int ihv = (h == 0) ? ih0 : ih1;
            const float* p = xb + idv * (HIN * WIN) + ihv * WIN;
            #pragma unroll
            for (int ic = 0; ic < 3; ic++) {
                const float* q = p + ic * XCH;
                float4 t = __ldg((const float4*)(q + iw0));  // 16B aligned (iw0%4==0)
                xv[a][h][ic][0] = t.x; xv[a][h][ic][1] = t.y;
                xv[a][h][ic][2] = t.z; xv[a][h][ic][3] = t.w;
                xv[a][h][ic][4] = __ldg(q + iw4);
            }
        }
    }

    float s[8];
    #pragma unroll
    for (int k = 0; k < 8; k++) s[k] = 0.f;

    #pragma unroll
    for (int oc = 0; oc < 16; oc++) {
        float v[8];
        #pragma unroll
        for (int k = 0; k < 8; k++) v[k] = 0.f;
        #pragma unroll
        for (int a = 0; a < ND; a++) {
            const int KD = (ND == 1) ? 1 : a * 2;
            #pragma unroll
            for (int h = 0; h < NH; h++) {
                const int KH = (NH == 1) ? 1 : h * 2;
                const float* g = sw + ((oc * 3 + KD) * 3 + KH) * 12;
                float4 A = *(const float4*)g;
                float4 B = *(const float4*)(g + 4);
                float  C = g[8];
                #pragma unroll
                for (int t = 0; t < 4; t++) {
                    float x0t = xv[a][h][0][t], x1t = xv[a][h][1][t], x2t = xv[a][h][2][t];
                    float x0n = xv[a][h][0][t+1], x1n = xv[a][h][1][t+1], x2n = xv[a][h][2][t+1];
                    v[2*t]   = fmaf(A.y, x0t, v[2*t]);
                    v[2*t]   = fmaf(B.x, x1t, v[2*t]);
                    v[2*t]   = fmaf(B.w, x2t, v[2*t]);
                    v[2*t+1] = fmaf(A.x, x0n, v[2*t+1]);
                    v[2*t+1] = fmaf(A.w, x1n, v[2*t+1]);
                    v[2*t+1] = fmaf(B.z, x2n, v[2*t+1]);
                    v[2*t+1] = fmaf(A.z, x0t, v[2*t+1]);
                    v[2*t+1] = fmaf(B.y, x1t, v[2*t+1]);
                    v[2*t+1] = fmaf(C,   x2t, v[2*t+1]);
                }
            }
        }
        #pragma unroll
        for (int k = 0; k < 8; k++) s[k] += __expf(v[k]);
    }

    int wb = 8 * c;
    #pragma unroll
    for (int k = 0; k < 7; k++) op[wb + k] = finish(s[k], bv);
    if (c < 7) op[wb + 7] = finish(s[7], bv);
}

// ---------------- width-4 path (class 3: odd od, odd oh) ----------------
__device__ __forceinline__ void run_quad22(
    const float* __restrict__ xb, const float* __restrict__ sw,
    float* __restrict__ op, int id0, int id1, int ih0, int ih1, int c, float bv)
{
    float xv[2][2][3][3];
    int iw0 = 2 * c;
    int iw2 = (c < 15) ? iw0 + 2 : 31;
    #pragma unroll
    for (int a = 0; a < 2; a++) {
        int idv = (a == 0) ? id0 : id1;
        #pragma unroll
        for (int h = 0; h < 2; h++) {
            int ihv = (h == 0) ? ih0 : ih1;
            const float* p = xb + idv * (HIN * WIN) + ihv * WIN;
            #pragma unroll
            for (int ic = 0; ic < 3; ic++) {
                const float* q = p + ic * XCH;
                float2 t = __ldg((const float2*)(q + iw0));
                xv[a][h][ic][0] = t.x;
                xv[a][h][ic][1] = t.y;
                xv[a][h][ic][2] = __ldg(q + iw2);
            }
        }
    }

    float s0 = 0.f, s1 = 0.f, s2 = 0.f, s3 = 0.f;
    #pragma unroll
    for (int oc = 0; oc < 16; oc++) {
        float v0 = 0.f, v1 = 0.f, v2 = 0.f, v3 = 0.f;
        #pragma unroll
        for (int a = 0; a < 2; a++) {
            const int KD = a * 2;
            #pragma unroll
            for (int h = 0; h < 2; h++) {
                const int KH = h * 2;
                const float* g = sw + ((oc * 3 + KD) * 3 + KH) * 12;
                float4 A = *(const float4*)g;
                float4 B = *(const float4*)(g + 4);
                float  C = g[8];
                float x00 = xv[a][h][0][0], x01 = xv[a][h][0][1], x02 = xv[a][h][0][2];
                float x10 = xv[a][h][1][0], x11 = xv[a][h][1][1], x12 = xv[a][h][1][2];
                float x20 = xv[a][h][2][0], x21 = xv[a][h][2][1], x22 = xv[a][h][2][2];
                v0 = fmaf(A.y, x00, v0); v0 = fmaf(B.x, x10, v0); v0 = fmaf(B.w, x20, v0);
                v2 = fmaf(A.y, x01, v2); v2 = fmaf(B.x, x11, v2); v2 = fmaf(B.w, x21, v2);
                v1 = fmaf(A.x, x01, v1); v1 = fmaf(A.w, x11, v1); v1 = fmaf(B.z, x21, v1);
                v1 = fmaf(A.z, x00, v1); v1 = fmaf(B.y, x10, v1); v1 = fmaf(C,   x20, v1);
                v3 = fmaf(A.x, x02, v3); v3 = fmaf(A.w, x12, v3); v3 = fmaf(B.z, x22, v3);
                v3 = fmaf(A.z, x01, v3); v3 = fmaf(B.y, x11, v3); v3 = fmaf(C,   x21, v3);
            }
        }
        s0 += __expf(v0); s1 += __expf(v1); s2 += __expf(v2); s3 += __expf(v3);
    }

    int wb = 4 * c;
    op[wb]     = finish(s0, bv);
    op[wb + 1] = finish(s1, bv);
    op[wb + 2] = finish(s2, bv);
    if (wb + 3 < 63) op[wb + 3] = finish(s3, bv);
}

// Merged kernel: one launch, class chosen by block range (cls3 FIRST: heaviest
// blocks start in wave 0 -> better tail packing). 2418 blocks total.
//   [0,930):      cls3, width-4, 16 rows/block (14880 rows)
//   [930,1442):   cls0, width-8, 32 rows/block (16384 rows)
//   [1442,1938):  cls1, width-8 (15872 rows)
//   [1938,2418):  cls2, width-8 (15360 rows)
__global__ __launch_bounds__(256)
void convT_lse_merged(const float* __restrict__ x, const float* __restrict__ w,
                      const float* __restrict__ bias, float* __restrict__ out)
{
    __shared__ __align__(16) float sw[WSH];
    load_weights(w, sw);
    __syncthreads();

    int warp = threadIdx.x >> 5, lane = threadIdx.x & 31;
    float bv = __ldg(bias);
    int blk = blockIdx.x;

    if (blk < 930) {
        // class 3 (odd od, odd oh), width 4
        int half = lane >> 4, c = lane & 15;
        int r = (blk * 8 + warp) * 2 + half;
        const int per_b = 15 * 31;
        int b = r / per_b; int rem = r - b * per_b;
        int idd = rem / 31; int ihh = rem - idd * 31;
        int od = 2 * idd + 1, oh = 2 * ihh + 1;
        const float* xb = x + (size_t)b * XB;
        float* op = out + ((size_t)(b * 31 + od) * 63 + oh) * 63;
        int id0 = (od + 1) >> 1, id1 = (od - 1) >> 1;
        int ih0 = (oh + 1) >> 1, ih1 = (oh - 1) >> 1;
        run_quad22(xb, sw, op, id0, id1, ih0, ih1, c, bv);
        return;
    }

    // width-8 classes
    int rloc = lane >> 3, c = lane & 7;
    int cls, rb;
    if (blk < 1442)      { cls = 0; rb = (blk - 930) * 32; }
    else if (blk < 1938) { cls = 1; rb = (blk - 1442) * 32; }
    else                 { cls = 2; rb = (blk - 1938) * 32; }
    int r = rb + warp * 4 + rloc;

    int pd = (cls == 2), ph = (cls == 1);
    int nhc = ph ? 31 : 32;
    int per_b = (pd ? 15 : 16) * nhc;
    int b = r / per_b; int rem = r - b * per_b;
    int idd = rem / nhc; int ihh = rem - idd * nhc;
    int od = 2 * idd + pd, oh = 2 * ihh + ph;

    const float* xb = x + (size_t)b * XB;
    float* op = out + ((size_t)(b * 31 + od) * 63 + oh) * 63;

    int id0, id1 = 0, ih0, ih1 = 0;
    if (pd) { id0 = (od + 1) >> 1; id1 = (od - 1) >> 1; } else id0 = od >> 1;
    if (ph) { ih0 = (oh + 1) >> 1; ih1 = (oh - 1) >> 1; } else ih0 = oh >> 1;

    if (cls == 0)      run_oct<1, 1>(xb, sw, op, id0, id1, ih0, ih1, c, bv);
    else if (cls == 1) run_oct<1, 2>(xb, sw, op, id0, id1, ih0, ih1, c, bv);
    else               run_oct<2, 1>(xb, sw, op, id0, id1, ih0, ih1, c, bv);
}

extern "C" void kernel_launch(void* const* d_in, const int* in_sizes, int n_in,
                              void* d_out, int out_size)
{
    const float* x    = (const float*)d_in[0];
    const float* w    = (const float*)d_in[1];
    const float* bias = (const float*)d_in[2];
    float* out        = (float*)d_out;

    convT_lse_merged<<<2418, 256>>>(x, w, bias, out);
}

// round 9
// speedup vs baseline: 1.3425x; 1.1137x over previous
#include <cuda_runtime.h>

// x: (32,3,16,32,32) fp32; weight: (3,16,3,3,3); bias scalar; out: (32,1,31,63,63)
// ConvTranspose3d s=2 p=1 k=3: per dim even o -> tap k=1 (i=o/2);
// odd o -> k=0 (i=(o+1)/2), k=2 (i=(o-1)/2). All in-range (od<=30, oh/ow<=62).

#define DIN 16
#define HIN 32
#define WIN 32
#define XCH (DIN*HIN*WIN)   // 16384
#define XB  (3*XCH)         // 49152
#define WSH (16*3*3*12)     // sw[oc][kd][kh][slot], slot=ic*3+kw (9 used, pad 12)
#define LOG2E 1.4426950408889634f

__device__ __forceinline__ float ex2f(float x) {
    float r; asm("ex2.approx.ftz.f32 %0, %1;" : "=f"(r) : "f"(x)); return r;
}

// Weights pre-scaled by log2(e): accumulators live in log2 domain, exp = single EX2.
__device__ __forceinline__ void load_weights(const float* __restrict__ w, float* sw) {
    // src w[ic*432 + oc*27 + kd*9 + kh*3 + kw]
    for (int i = threadIdx.x; i < 1296; i += 128) {
        int ic = i / 432;  int r = i - ic * 432;
        int oc = r / 27;   int tap = r - oc * 27;
        int kd = tap / 9;  int t2 = tap - kd * 9;
        int kh = t2 / 3;   int kw = t2 - kh * 3;
        sw[((oc * 3 + kd) * 3 + kh) * 12 + ic * 3 + kw] = w[i] * LOG2E;
    }
}

__device__ __forceinline__ float finish(float s, float bv) {
    float l = __logf(s);   // s = sum e^conv (exact natural-log domain)
    float h = __fdividef(l, 6.f * (1.f + __expf(-(l + 3.f))));
    return fminf(fmaxf(h - bv, -1.f), 1.f);
}

// ---------------- width-8 path (classes with ND*NH <= 2) ----------------
// Lane c = lane&7 handles ow = 8c..8c+7 (c==7: ow 63 masked). 4 rows per warp.
template<int ND, int NH>
__device__ __forceinline__ void run_oct(
    const float* __restrict__ xb, const float* __restrict__ sw,
    float* __restrict__ op, int id0, int id1, int ih0, int ih1, int c, float bv)
{
    float xv[ND][NH][3][5];
    int iw0 = 4 * c;
    int iw4 = (c < 7) ? iw0 + 4 : 31;   // clamp; only feeds masked ow=63
    #pragma unroll
    for (int a = 0; a < ND; a++) {
        int idv = (a == 0) ? id0 : id1;
        #pragma unroll
        for (int h = 0; h < NH; h++) {
            int ihv = (h == 0) ? ih0 : ih1;
            const float* p = xb + idv * (HIN * WIN) + ihv * WIN;
            #pragma unroll
            for (int ic = 0; ic < 3; ic++) {
                const float* q = p + ic * XCH;
                float4 t = __ldg((const float4*)(q + iw0));  // 16B aligned
                xv[a][h][ic][0] = t.x; xv[a][h][ic][1] = t.y;
                xv[a][h][ic][2] = t.z; xv[a][h][ic][3] = t.w;
                xv[a][h][ic][4] = __ldg(q + iw4);
            }
        }
    }

    float s[8];
    #pragma unroll
    for (int k = 0; k < 8; k++) s[k] = 0.f;

    #pragma unroll
    for (int oc = 0; oc < 16; oc++) {
        float v[8];
        #pragma unroll
        for (int k = 0; k < 8; k++) v[k] = 0.f;
        #pragma unroll
        for (int a = 0; a < ND; a++) {
            const int KD = (ND == 1) ? 1 : a * 2;
            #pragma unroll
            for (int h = 0; h < NH; h++) {
                const int KH = (NH == 1) ? 1 : h * 2;
                const float* g = sw + ((oc * 3 + KD) * 3 + KH) * 12;
                float4 A = *(const float4*)g;
                float4 B = *(const float4*)(g + 4);
                float  C = g[8];
                #pragma unroll
                for (int t = 0; t < 4; t++) {
                    float x0t = xv[a][h][0][t], x1t = xv[a][h][1][t], x2t = xv[a][h][2][t];
                    float x0n = xv[a][h][0][t+1], x1n = xv[a][h][1][t+1], x2n = xv[a][h][2][t+1];
                    v[2*t]   = fmaf(A.y, x0t, v[2*t]);
                    v[2*t]   = fmaf(B.x, x1t, v[2*t]);
                    v[2*t]   = fmaf(B.w, x2t, v[2*t]);
                    v[2*t+1] = fmaf(A.x, x0n, v[2*t+1]);
                    v[2*t+1] = fmaf(A.w, x1n, v[2*t+1]);
                    v[2*t+1] = fmaf(B.z, x2n, v[2*t+1]);
                    v[2*t+1] = fmaf(A.z, x0t, v[2*t+1]);
                    v[2*t+1] = fmaf(B.y, x1t, v[2*t+1]);
                    v[2*t+1] = fmaf(C,   x2t, v[2*t+1]);
                }
            }
        }
        #pragma unroll
        for (int k = 0; k < 8; k++) s[k] += ex2f(v[k]);   // v in log2 domain
    }

    int wb = 8 * c;
    #pragma unroll
    for (int k = 0; k < 7; k++) op[wb + k] = finish(s[k], bv);
    if (c < 7) op[wb + 7] = finish(s[7], bv);
}

// ---------------- width-4 path (class 3: odd od, odd oh) ----------------
__device__ __forceinline__ void run_quad22(
    const float* __restrict__ xb, const float* __restrict__ sw,
    float* __restrict__ op, int id0, int id1, int ih0, int ih1, int c, float bv)
{
    float xv[2][2][3][3];
    int iw0 = 2 * c;
    int iw2 = (c < 15) ? iw0 + 2 : 31;
    #pragma unroll
    for (int a = 0; a < 2; a++) {
        int idv = (a == 0) ? id0 : id1;
        #pragma unroll
        for (int h = 0; h < 2; h++) {
            int ihv = (h == 0) ? ih0 : ih1;
            const float* p = xb + idv * (HIN * WIN) + ihv * WIN;
            #pragma unroll
            for (int ic = 0; ic < 3; ic++) {
                const float* q = p + ic * XCH;
                float2 t = __ldg((const float2*)(q + iw0));
                xv[a][h][ic][0] = t.x;
                xv[a][h][ic][1] = t.y;
                xv[a][h][ic][2] = __ldg(q + iw2);
            }
        }
    }

    float s0 = 0.f, s1 = 0.f, s2 = 0.f, s3 = 0.f;
    #pragma unroll
    for (int oc = 0; oc < 16; oc++) {
        float v0 = 0.f, v1 = 0.f, v2 = 0.f, v3 = 0.f;
        #pragma unroll
        for (int a = 0; a < 2; a++) {
            const int KD = a * 2;
            #pragma unroll
            for (int h = 0; h < 2; h++) {
                const int KH = h * 2;
                const float* g = sw + ((oc * 3 + KD) * 3 + KH) * 12;
                float4 A = *(const float4*)g;
                float4 B = *(const float4*)(g + 4);
                float  C = g[8];
                float x00 = xv[a][h][0][0], x01 = xv[a][h][0][1], x02 = xv[a][h][0][2];
                float x10 = xv[a][h][1][0], x11 = xv[a][h][1][1], x12 = xv[a][h][1][2];
                float x20 = xv[a][h][2][0], x21 = xv[a][h][2][1], x22 = xv[a][h][2][2];
                v0 = fmaf(A.y, x00, v0); v0 = fmaf(B.x, x10, v0); v0 = fmaf(B.w, x20, v0);
                v2 = fmaf(A.y, x01, v2); v2 = fmaf(B.x, x11, v2); v2 = fmaf(B.w, x21, v2);
                v1 = fmaf(A.x, x01, v1); v1 = fmaf(A.w, x11, v1); v1 = fmaf(B.z, x21, v1);
                v1 = fmaf(A.z, x00, v1); v1 = fmaf(B.y, x10, v1); v1 = fmaf(C,   x20, v1);
                v3 = fmaf(A.x, x02, v3); v3 = fmaf(A.w, x12, v3); v3 = fmaf(B.z, x22, v3);
                v3 = fmaf(A.z, x01, v3); v3 = fmaf(B.y, x11, v3); v3 = fmaf(C,   x21, v3);
            }
        }
        s0 += ex2f(v0); s1 += ex2f(v1); s2 += ex2f(v2); s3 += ex2f(v3);
    }

    int wb = 4 * c;
    op[wb]     = finish(s0, bv);
    op[wb + 1] = finish(s1, bv);
    op[wb + 2] = finish(s2, bv);
    if (wb + 3 < 63) op[wb + 3] = finish(s3, bv);
}

// Merged kernel, 128-thread blocks (4 warps) for register-file packing.
// Block ranges (cls3 first = heaviest blocks start in wave 0):
//   [0,1860):     cls3, width-4,  8 rows/block (14880 rows)
//   [1860,2884):  cls0, width-8, 16 rows/block (16384 rows)
//   [2884,3876):  cls1, width-8 (15872 rows)
//   [3876,4836):  cls2, width-8 (15360 rows)
__global__ __launch_bounds__(128)
void convT_lse_v9(const float* __restrict__ x, const float* __restrict__ w,
                  const float* __restrict__ bias, float* __restrict__ out)
{
    __shared__ __align__(16) float sw[WSH];
    load_weights(w, sw);
    __syncthreads();

    int warp = threadIdx.x >> 5, lane = threadIdx.x & 31;
    float bv = __ldg(bias);
    int blk = blockIdx.x;

    if (blk < 1860) {
        // class 3 (odd od, odd oh), width 4, 8 rows/block
        int half = lane >> 4, c = lane & 15;
        int r = (blk * 4 + warp) * 2 + half;
        const int per_b = 15 * 31;
        int b = r / per_b; int rem = r - b * per_b;
        int idd = rem / 31; int ihh = rem - idd * 31;
        int od = 2 * idd + 1, oh = 2 * ihh + 1;
        const float* xb = x + (size_t)b * XB;
        float* op = out + ((size_t)(b * 31 + od) * 63 + oh) * 63;
        int id0 = (od + 1) >> 1, id1 = (od - 1) >> 1;
        int ih0 = (oh + 1) >> 1, ih1 = (oh - 1) >> 1;
        run_quad22(xb, sw, op, id0, id1, ih0, ih1, c, bv);
        return;
    }

    // width-8 classes, 16 rows/block
    int rloc = lane >> 3, c = lane & 7;
    int cls, rb;
    if (blk < 2884)      { cls = 0; rb = (blk - 1860) * 16; }
    else if (blk < 3876) { cls = 1; rb = (blk - 2884) * 16; }
    else                 { cls = 2; rb = (blk - 3876) * 16; }
    int r = rb + warp * 4 + rloc;

    int pd = (cls == 2), ph = (cls == 1);
    int nhc = ph ? 31 : 32;
    int per_b = (pd ? 15 : 16) * nhc;
    int b = r / per_b; int rem = r - b * per_b;
    int idd = rem / nhc; int ihh = rem - idd * nhc;
    int od = 2 * idd + pd, oh = 2 * ihh + ph;

    const float* xb = x + (size_t)b * XB;
    float* op = out + ((size_t)(b * 31 + od) * 63 + oh) * 63;

    int id0, id1 = 0, ih0, ih1 = 0;
    if (pd) { id0 = (od + 1) >> 1; id1 = (od - 1) >> 1; } else id0 = od >> 1;
    if (ph) { ih0 = (oh + 1) >> 1; ih1 = (oh - 1) >> 1; } else ih0 = oh >> 1;

    if (cls == 0)      run_oct<1, 1>(xb, sw, op, id0, id1, ih0, ih1, c, bv);
    else if (cls == 1) run_oct<1, 2>(xb, sw, op, id0, id1, ih0, ih1, c, bv);
    else               run_oct<2, 1>(xb, sw, op, id0, id1, ih0, ih1, c, bv);
}

extern "C" void kernel_launch(void* const* d_in, const int* in_sizes, int n_in,
                              void* d_out, int out_size)
{
    const float* x    = (const float*)d_in[0];
    const float* w    = (const float*)d_in[1];
    const float* bias = (const float*)d_in[2];
    float* out        = (float*)d_out;

    convT_lse_v9<<<4836, 128>>>(x, w, bias, out);
}

// round 10
// speedup vs baseline: 1.3497x; 1.0054x over previous
#include <cuda_runtime.h>

// x: (32,3,16,32,32) fp32; weight: (3,16,3,3,3); bias scalar; out: (32,1,31,63,63)
// ConvTranspose3d s=2 p=1 k=3: per dim even o -> tap k=1 (i=o/2);
// odd o -> k=0 (i=(o+1)/2), k=2 (i=(o-1)/2). All in-range (od<=30, oh/ow<=62).

#define DIN 16
#define HIN 32
#define WIN 32
#define XCH (DIN*HIN*WIN)   // 16384
#define XB  (3*XCH)         // 49152
#define WSH (16*3*3*12)     // sw[oc][kd][kh][slot], slot=ic*3+kw (9 used, pad 12)
#define LOG2E 1.4426950408889634f

__device__ __forceinline__ float ex2f(float x) {
    float r; asm("ex2.approx.ftz.f32 %0, %1;" : "=f"(r) : "f"(x)); return r;
}

// Weights pre-scaled by log2(e): conv accumulators live in log2 domain; exp = one EX2.
__device__ __forceinline__ void load_weights(const float* __restrict__ w, float* sw) {
    // src w[ic*432 + oc*27 + kd*9 + kh*3 + kw]
    for (int i = threadIdx.x; i < 1296; i += 128) {
        int ic = i / 432;  int r = i - ic * 432;
        int oc = r / 27;   int tap = r - oc * 27;
        int kd = tap / 9;  int t2 = tap - kd * 9;
        int kh = t2 / 3;   int kw = t2 - kh * 3;
        sw[((oc * 3 + kd) * 3 + kh) * 12 + ic * 3 + kw] = w[i] * LOG2E;
    }
}

__device__ __forceinline__ float finish(float s, float bv) {
    float l = __logf(s);   // s = sum e^conv
    // sigmoid denom: e^{-(l+3)} = 2^{-(l+3)*log2e} -> one FMA + one EX2
    float e = ex2f(fmaf(l, -LOG2E, -3.0f * LOG2E));
    float h = l * __frcp_rn((1.f + e) * 6.f);
    return fminf(fmaxf(h - bv, -1.f), 1.f);
}

// ---------------- width-8 path (classes with ND*NH <= 2) ----------------
// Lane c = lane&7 handles ow = 8c..8c+7 (c==7: ow 63 masked). 4 rows per warp.
template<int ND, int NH>
__device__ __forceinline__ void run_oct(
    const float* __restrict__ xb, const float* __restrict__ sw,
    float* __restrict__ op, int id0, int id1, int ih0, int ih1, int c, float bv)
{
    float xv[ND][NH][3][5];
    int iw0 = 4 * c;
    int iw4 = (c < 7) ? iw0 + 4 : 31;   // clamp; only feeds masked ow=63
    #pragma unroll
    for (int a = 0; a < ND; a++) {
        int idv = (a == 0) ? id0 : id1;
        #pragma unroll
        for (int h = 0; h < NH; h++) {
            int ihv = (h == 0) ? ih0 : ih1;
            const float* p = xb + idv * (HIN * WIN) + ihv * WIN;
            #pragma unroll
            for (int ic = 0; ic < 3; ic++) {
                const float* q = p + ic * XCH;
                float4 t = __ldg((const float4*)(q + iw0));  // 16B aligned
                xv[a][h][ic][0] = t.x; xv[a][h][ic][1] = t.y;
                xv[a][h][ic][2] = t.z; xv[a][h][ic][3] = t.w;
                xv[a][h][ic][4] = __ldg(q + iw4);
            }
        }
    }

    float s[8];
    #pragma unroll
    for (int k = 0; k < 8; k++) s[k] = 0.f;

    #pragma unroll
    for (int oc = 0; oc < 16; oc++) {
        float v[8];
        #pragma unroll
        for (int k = 0; k < 8; k++) v[k] = 0.f;
        #pragma unroll
        for (int a = 0; a < ND; a++) {
            const int KD = (ND == 1) ? 1 : a * 2;
            #pragma unroll
            for (int h = 0; h < NH; h++) {
                const int KH = (NH == 1) ? 1 : h * 2;
                const float* g = sw + ((oc * 3 + KD) * 3 + KH) * 12;
                float4 A = *(const float4*)g;
                float4 B = *(const float4*)(g + 4);
                float  C = g[8];
                #pragma unroll
                for (int t = 0; t < 4; t++) {
                    float x0t = xv[a][h][0][t], x1t = xv[a][h][1][t], x2t = xv[a][h][2][t];
                    float x0n = xv[a][h][0][t+1], x1n = xv[a][h][1][t+1], x2n = xv[a][h][2][t+1];
                    v[2*t]   = fmaf(A.y, x0t, v[2*t]);
                    v[2*t]   = fmaf(B.x, x1t, v[2*t]);
                    v[2*t]   = fmaf(B.w, x2t, v[2*t]);
                    v[2*t+1] = fmaf(A.x, x0n, v[2*t+1]);
                    v[2*t+1] = fmaf(A.w, x1n, v[2*t+1]);
                    v[2*t+1] = fmaf(B.z, x2n, v[2*t+1]);
                    v[2*t+1] = fmaf(A.z, x0t, v[2*t+1]);
                    v[2*t+1] = fmaf(B.y, x1t, v[2*t+1]);
                    v[2*t+1] = fmaf(C,   x2t, v[2*t+1]);
                }
            }
        }
        #pragma unroll
        for (int k = 0; k < 8; k++) s[k] += ex2f(v[k]);   // v in log2 domain
    }

    int wb = 8 * c;
    #pragma unroll
    for (int k = 0; k < 7; k++) op[wb + k] = finish(s[k], bv);
    if (c < 7) op[wb + 7] = finish(s[7], bv);
}

// ---------------- width-4 path (class 3: odd od, odd oh) ----------------
__device__ __forceinline__ void run_quad22(
    const float* __restrict__ xb, const float* __restrict__ sw,
    float* __restrict__ op, int id0, int id1, int ih0, int ih1, int c, float bv)
{
    float xv[2][2][3][3];
    int iw0 = 2 * c;
    int iw2 = (c < 15) ? iw0 + 2 : 31;
    #pragma unroll
    for (int a = 0; a < 2; a++) {
        int idv = (a == 0) ? id0 : id1;
        #pragma unroll
        for (int h = 0; h < 2; h++) {
            int ihv = (h == 0) ? ih0 : ih1;
            const float* p = xb + idv * (HIN * WIN) + ihv * WIN;
            #pragma unroll
            for (int ic = 0; ic < 3; ic++) {
                const float* q = p + ic * XCH;
                float2 t = __ldg((const float2*)(q + iw0));
                xv[a][h][ic][0] = t.x;
                xv[a][h][ic][1] = t.y;
                xv[a][h][ic][2] = __ldg(q + iw2);
            }
        }
    }

    float s0 = 0.f, s1 = 0.f, s2 = 0.f, s3 = 0.f;
    #pragma unroll
    for (int oc = 0; oc < 16; oc++) {
        float v0 = 0.f, v1 = 0.f, v2 = 0.f, v3 = 0.f;
        #pragma unroll
        for (int a = 0; a < 2; a++) {
            const int KD = a * 2;
            #pragma unroll
            for (int h = 0; h < 2; h++) {
                const int KH = h * 2;
                const float* g = sw + ((oc * 3 + KD) * 3 + KH) * 12;
                float4 A = *(const float4*)g;
                float4 B = *(const float4*)(g + 4);
                float  C = g[8];
                float x00 = xv[a][h][0][0], x01 = xv[a][h][0][1], x02 = xv[a][h][0][2];
                float x10 = xv[a][h][1][0], x11 = xv[a][h][1][1], x12 = xv[a][h][1][2];
                float x20 = xv[a][h][2][0], x21 = xv[a][h][2][1], x22 = xv[a][h][2][2];
                v0 = fmaf(A.y, x00, v0); v0 = fmaf(B.x, x10, v0); v0 = fmaf(B.w, x20, v0);
                v2 = fmaf(A.y, x01, v2); v2 = fmaf(B.x, x11, v2); v2 = fmaf(B.w, x21, v2);
                v1 = fmaf(A.x, x01, v1); v1 = fmaf(A.w, x11, v1); v1 = fmaf(B.z, x21, v1);
                v1 = fmaf(A.z, x00, v1); v1 = fmaf(B.y, x10, v1); v1 = fmaf(C,   x20, v1);
                v3 = fmaf(A.x, x02, v3); v3 = fmaf(A.w, x12, v3); v3 = fmaf(B.z, x22, v3);
                v3 = fmaf(A.z, x01, v3); v3 = fmaf(B.y, x11, v3); v3 = fmaf(C,   x21, v3);
            }
        }
        s0 += ex2f(v0); s1 += ex2f(v1); s2 += ex2f(v2); s3 += ex2f(v3);
    }

    int wb = 4 * c;
    op[wb]     = finish(s0, bv);
    op[wb + 1] = finish(s1, bv);
    op[wb + 2] = finish(s2, bv);
    if (wb + 3 < 63) op[wb + 3] = finish(s3, bv);
}

// Merged kernel, 128-thread blocks, min 8 blocks/SM (forces regs <= 64).
// Block ranges (cls3 first = heaviest blocks start in wave 0):
//   [0,1860):     cls3, width-4,  8 rows/block (14880 rows)
//   [1860,2884):  cls0, width-8, 16 rows/block (16384 rows)
//   [2884,3876):  cls1, width-8 (15872 rows)
//   [3876,4836):  cls2, width-8 (15360 rows)
__global__ __launch_bounds__(128, 8)
void convT_lse_v10(const float* __restrict__ x, const float* __restrict__ w,
                   const float* __restrict__ bias, float* __restrict__ out)
{
    __shared__ __align__(16) float sw[WSH];
    load_weights(w, sw);
    __syncthreads();

    int warp = threadIdx.x >> 5, lane = threadIdx.x & 31;
    float bv = __ldg(bias);
    int blk = blockIdx.x;

    if (blk < 1860) {
        // class 3 (odd od, odd oh), width 4, 8 rows/block
        int half = lane >> 4, c = lane & 15;
        int r = (blk * 4 + warp) * 2 + half;
        const int per_b = 15 * 31;
        int b = r / per_b; int rem = r - b * per_b;
        int idd = rem / 31; int ihh = rem - idd * 31;
        int od = 2 * idd + 1, oh = 2 * ihh + 1;
        const float* xb = x + (size_t)b * XB;
        float* op = out + ((size_t)(b * 31 + od) * 63 + oh) * 63;
        int id0 = (od + 1) >> 1, id1 = (od - 1) >> 1;
        int ih0 = (oh + 1) >> 1, ih1 = (oh - 1) >> 1;
        run_quad22(xb, sw, op, id0, id1, ih0, ih1, c, bv);
        return;
    }

    // width-8 classes, 16 rows/block
    int rloc = lane >> 3, c = lane & 7;
    int cls, rb;
    if (blk < 2884)      { cls = 0; rb = (blk - 1860) * 16; }
    else if (blk < 3876) { cls = 1; rb = (blk - 2884) * 16; }
    else                 { cls = 2; rb = (blk - 3876) * 16; }
    int r = rb + warp * 4 + rloc;

    int pd = (cls == 2), ph = (cls == 1);
    int nhc = ph ? 31 : 32;
    int per_b = (pd ? 15 : 16) * nhc;
    int b = r / per_b; int rem = r - b * per_b;
    int idd = rem / nhc; int ihh = rem - idd * nhc;
    int od = 2 * idd + pd, oh = 2 * ihh + ph;

    const float* xb = x + (size_t)b * XB;
    float* op = out + ((size_t)(b * 31 + od) * 63 + oh) * 63;

    int id0, id1 = 0, ih0, ih1 = 0;
    if (pd) { id0 = (od + 1) >> 1; id1 = (od - 1) >> 1; } else id0 = od >> 1;
    if (ph) { ih0 = (oh + 1) >> 1; ih1 = (oh - 1) >> 1; } else ih0 = oh >> 1;

    if (cls == 0)      run_oct<1, 1>(xb, sw, op, id0, id1, ih0, ih1, c, bv);
    else if (cls == 1) run_oct<1, 2>(xb, sw, op, id0, id1, ih0, ih1, c, bv);
    else               run_oct<2, 1>(xb, sw, op, id0, id1, ih0, ih1, c, bv);
}

extern "C" void kernel_launch(void* const* d_in, const int* in_sizes, int n_in,
                              void* d_out, int out_size)
{
    const float* x    = (const float*)d_in[0];
    const float* w    = (const float*)d_in[1];
    const float* bias = (const float*)d_in[2];
    float* out        = (float*)d_out;

    convT_lse_v10<<<4836, 128>>>(x, w, bias, out);
}